// round 2
// baseline (speedup 1.0000x reference)
#include <cuda_runtime.h>
#include <cuda_bf16.h>

#define TSTEPS 400
#define RPB    128      // rows per block == threads per block
#define SSTR   68       // smem row stride in floats (64 data + 4 pad, bank-conflict-free)

// Exact reference simulation for rare rows (trailing run >= 16 or fewer than
// 2 corrects in the first 32 steps). Matches the JAX reference op-for-op.
__device__ __noinline__ float sm2_slow_row(const float* __restrict__ row) {
    float I = 1.0f, n = 0.0f, EF = 2.5f;
    for (int t = 0; t < TSTEPS; ++t) {
        float p = row[t];
        float q = p * 5.0f;
        bool correct = (q >= 3.0f);
        bool brk = (p == -1.0f);
        float In;
        if (n >= 2.0f)      In = I * EF;
        else if (n == 1.0f) In = 6.0f;
        else                In = 1.0f;
        if (!correct) In = 1.0f;
        if (!brk) I = In;
        I = fminf(fmaxf(I, 1.0f), 274.0f);
        float d = 5.0f - q;
        EF = EF + (0.1f - d * (0.08f + d * 0.02f));
        EF = fmaxf(EF, 1.3f);
        if (correct) n += 1.0f;
    }
    return I;
}

// EF recursion step: E' = max(E + (0.1 - d*(0.08+0.02d)), 1.3), d = 5 - 5p.
__device__ __forceinline__ float ef_step(float E, float pv) {
    float d  = fmaf(pv, -5.0f, 5.0f);
    float t2 = fmaf(d, 0.02f, 0.08f);
    float dl = fmaf(-d, t2, 0.1f);
    return fmaxf(E + dl, 1.3f);
}

__global__ void __launch_bounds__(RPB)
sm2_kernel(const float* __restrict__ p, float* __restrict__ out, int B) {
    __shared__ float sbuf[RPB * SSTR];

    const int t  = threadIdx.x;
    const int w  = t >> 5;           // warp 0..3
    const int l  = t & 31;           // lane
    const int rowBase = blockIdx.x * RPB;
    const float* gbase = p + (size_t)rowBase * TSTEPS;

    const bool full = (rowBase + RPB <= B);

    float E = 2.5f;
    int   cnt2 = 0;      // corrects in first 32 steps
    float Eh[16];        // E_t for t in [384, 399]
    unsigned mask = 0u;  // correctness bits for t in [384, 399]

    if (full) {
        // ---- 6 full chunks of 64 steps ----
        #pragma unroll 1
        for (int c = 0; c < 6; ++c) {
            // Coalesced load: 16 lanes cover one row's 256B; 2 rows per warp instr.
            #pragma unroll
            for (int i = 0; i < 16; ++i) {
                int row = (w << 5) + (i << 1) + (l >> 4);
                int c4  = l & 15;
                float4 v = *reinterpret_cast<const float4*>(
                    gbase + (size_t)row * TSTEPS + c * 64 + c4 * 4);
                *reinterpret_cast<float4*>(sbuf + row * SSTR + c4 * 4) = v;
            }
            __syncthreads();

            // Thread t scans row t's 64 steps from smem (conflict-free LDS.128).
            if (c == 0) {
                #pragma unroll
                for (int j = 0; j < 16; ++j) {
                    float4 v = *reinterpret_cast<const float4*>(sbuf + t * SSTR + j * 4);
                    float pv[4] = {v.x, v.y, v.z, v.w};
                    #pragma unroll
                    for (int k = 0; k < 4; ++k) {
                        E = ef_step(E, pv[k]);
                        if (j < 8) cnt2 += (pv[k] * 5.0f >= 3.0f);
                    }
                }
            } else {
                #pragma unroll
                for (int j = 0; j < 16; ++j) {
                    float4 v = *reinterpret_cast<const float4*>(sbuf + t * SSTR + j * 4);
                    float pv[4] = {v.x, v.y, v.z, v.w};
                    #pragma unroll
                    for (int k = 0; k < 4; ++k)
                        E = ef_step(E, pv[k]);
                }
            }
            __syncthreads();
        }

        // ---- tail: 16 steps (t = 384..399) ----
        #pragma unroll
        for (int i = 0; i < 4; ++i) {
            int row = (w << 5) + (i << 3) + (l >> 2);
            int c4  = l & 3;
            float4 v = *reinterpret_cast<const float4*>(
                gbase + (size_t)row * TSTEPS + 384 + c4 * 4);
            *reinterpret_cast<float4*>(sbuf + row * SSTR + c4 * 4) = v;
        }
        __syncthreads();

        #pragma unroll
        for (int j = 0; j < 4; ++j) {
            float4 v = *reinterpret_cast<const float4*>(sbuf + t * SSTR + j * 4);
            float pv[4] = {v.x, v.y, v.z, v.w};
            #pragma unroll
            for (int k = 0; k < 4; ++k) {
                E = ef_step(E, pv[k]);
                Eh[j * 4 + k] = E;
                mask |= (pv[k] * 5.0f >= 3.0f) ? (1u << (j * 4 + k)) : 0u;
            }
        }
    } else {
        // Partial block (B not a multiple of RPB): per-thread fallback.
        int b = rowBase + t;
        if (b < B) out[b] = fminf(2.0f * sm2_slow_row(p + (size_t)b * TSTEPS), 274.0f);
        return;
    }

    // ---- epilogue (identical logic to the validated R1 kernel) ----
    int b = rowBase + t;
    // L = length of trailing run of corrects within the last 16 steps.
    int L = __clz(((~mask) & 0xFFFFu) << 16);   // mask==0xFFFF -> L=32 -> slow path

    float I;
    if (L <= 15 && cnt2 >= 2) {
        // Final I = min( prod of the trailing-run E values, 274 ); factors >= 1.3
        // so progressive clip == final clip.
        float prod = 1.0f;
        #pragma unroll
        for (int j = 0; j < 15; ++j)
            if (j >= 15 - L) prod = fminf(prod * Eh[j], 274.0f);
        I = (L == 0) ? 1.0f : prod;
    } else {
        I = sm2_slow_row(p + (size_t)b * TSTEPS);   // rare: ~1-3 rows in 524288
    }

    // h = clip(I / 0.5, 15/1440, 274); 2I >= 2 > OUT_MIN always.
    out[b] = fminf(2.0f * I, 274.0f);
}

extern "C" void kernel_launch(void* const* d_in, const int* in_sizes, int n_in,
                              void* d_out, int out_size) {
    const float* p = (const float*)d_in[0];
    float* out = (float*)d_out;
    int B = out_size;
    int blocks = (B + RPB - 1) / RPB;
    sm2_kernel<<<blocks, RPB>>>(p, out, B);
}

// round 3
// speedup vs baseline: 1.3565x; 1.3565x over previous
#include <cuda_runtime.h>
#include <cuda_bf16.h>

#define TSTEPS 400
#define NEG_INF __int_as_float(0xff800000)

// Exact reference simulation for rare rows (trailing run >= 16 or fewer than
// 2 corrects in the first 32 steps). Matches the JAX reference op-for-op.
__device__ __noinline__ float sm2_slow_row(const float* __restrict__ row) {
    float I = 1.0f, n = 0.0f, EF = 2.5f;
    for (int t = 0; t < TSTEPS; ++t) {
        float p = row[t];
        float q = p * 5.0f;
        bool correct = (q >= 3.0f);
        bool brk = (p == -1.0f);
        float In;
        if (n >= 2.0f)      In = I * EF;
        else if (n == 1.0f) In = 6.0f;
        else                In = 1.0f;
        if (!correct) In = 1.0f;
        if (!brk) I = In;
        I = fminf(fmaxf(I, 1.0f), 274.0f);
        float d = 5.0f - q;
        EF = EF + (0.1f - d * (0.08f + d * 0.02f));
        EF = fmaxf(EF, 1.3f);
        if (correct) n += 1.0f;
    }
    return I;
}

// delta(p) = 0.1 - d*(0.08 + 0.02 d),  d = 5 - 5p  (same FMA shape as validated R1)
__device__ __forceinline__ float delta_of(float pv) {
    float d  = fmaf(pv, -5.0f, 5.0f);
    float t2 = fmaf(d, 0.02f, 0.08f);
    return fmaf(-d, t2, 0.1f);
}

__global__ void __launch_bounds__(256)
sm2_kernel(const float* __restrict__ p, float* __restrict__ out, int B) {
    const unsigned FULL = 0xFFFFFFFFu;
    int gwarp = (blockIdx.x * blockDim.x + threadIdx.x) >> 5;
    int lane  = threadIdx.x & 31;
    int q     = lane & 7;              // position within 8-lane row group

    int row0 = gwarp * 4 + (lane >> 3);
    int row  = (row0 < B) ? row0 : (B - 1);   // clamp: keep full warp active for shfl
    const float* rp = p + (size_t)row * TSTEPS;

    // Carry composition (S, M) over processed prefix: E = max(E0 + S, M).
    float S = 0.0f, M = NEG_INF;
    int cnt2 = 0;

    // Register double-buffered prefetch, depth 2.
    float4 buf0 = *reinterpret_cast<const float4*>(rp + 0 * 32 + q * 4);
    float4 buf1 = *reinterpret_cast<const float4*>(rp + 1 * 32 + q * 4);

    #pragma unroll
    for (int j = 0; j < 12; ++j) {
        float4 v = (j & 1) ? buf1 : buf0;
        if (j + 2 < 12) {
            float4 nv = *reinterpret_cast<const float4*>(rp + (j + 2) * 32 + q * 4);
            if (j & 1) buf1 = nv; else buf0 = nv;
        }
        float pv[4] = {v.x, v.y, v.z, v.w};

        // Local composition over this lane's 4 consecutive steps.
        float s = 0.0f, m = NEG_INF;
        #pragma unroll
        for (int k = 0; k < 4; ++k) {
            float dl = delta_of(pv[k]);
            m = fmaxf(m + dl, 1.3f);
            s += dl;
        }

        if (j == 0) {
            // corrects in t in [0,32): exactly this chunk. Butterfly sum (commutative).
            int c = 0;
            #pragma unroll
            for (int k = 0; k < 4; ++k) c += (pv[k] * 5.0f >= 3.0f);
            c += __shfl_xor_sync(FULL, c, 1, 8);
            c += __shfl_xor_sync(FULL, c, 2, 8);
            c += __shfl_xor_sync(FULL, c, 4, 8);
            cnt2 = c;   // valid on all lanes
        }

        // Ordered tree reduce across the 8 lanes (ascending offsets => adjacent
        // segments combine; leader q==0 ends with the full 32-step composition).
        #pragma unroll
        for (int off = 1; off <= 4; off <<= 1) {
            float so = __shfl_down_sync(FULL, s, off, 8);
            float mo = __shfl_down_sync(FULL, m, off, 8);
            m = fmaxf(m + so, mo);   // self earlier, other later
            s = s + so;
        }

        // Compose chunk into carry (meaningful on leader; harmless elsewhere).
        M = fmaxf(M + s, m);
        S = S + s;
    }

    // Broadcast leader's carry; E_383 = max(2.5 + S, M).
    float Sg = __shfl_sync(FULL, S, 0, 8);
    float Mg = __shfl_sync(FULL, M, 0, 8);
    float E  = fmaxf(2.5f + Sg, Mg);

    // Tail t = 384..399: sequential, redundantly on all 8 lanes (broadcast loads).
    float Eh[16];
    unsigned mask = 0u;
    #pragma unroll
    for (int j = 0; j < 4; ++j) {
        float4 v = *reinterpret_cast<const float4*>(rp + 384 + j * 4);
        float pv[4] = {v.x, v.y, v.z, v.w};
        #pragma unroll
        for (int k = 0; k < 4; ++k) {
            E = fmaxf(E + delta_of(pv[k]), 1.3f);
            Eh[j * 4 + k] = E;
            mask |= (pv[k] * 5.0f >= 3.0f) ? (1u << (j * 4 + k)) : 0u;
        }
    }

    // L = trailing-correct run length within last 16 steps (mask==0xFFFF -> 32 -> slow).
    int L = __clz(((~mask) & 0xFFFFu) << 16);

    float I;
    if (L <= 15 && cnt2 >= 2) {
        // Final I = min( prod of trailing-run E values, 274 ); factors >= 1.3 so
        // progressive clip == final clip. (Identical to validated R1 epilogue.)
        float prod = 1.0f;
        #pragma unroll
        for (int j = 0; j < 15; ++j)
            if (j >= 15 - L) prod = fminf(prod * Eh[j], 274.0f);
        I = (L == 0) ? 1.0f : prod;
    } else {
        I = sm2_slow_row(rp);   // rare (~1e-6 of rows); group-uniform divergence
    }

    if (q == 0 && row0 < B)
        out[row] = fminf(2.0f * I, 274.0f);
}

extern "C" void kernel_launch(void* const* d_in, const int* in_sizes, int n_in,
                              void* d_out, int out_size) {
    const float* p = (const float*)d_in[0];
    float* out = (float*)d_out;
    int B = out_size;
    int rowsPerBlock = 32;                 // 256 threads = 8 warps * 4 rows
    int blocks = (B + rowsPerBlock - 1) / rowsPerBlock;
    sm2_kernel<<<blocks, 256>>>(p, out, B);
}

// round 4
// speedup vs baseline: 2.2419x; 1.6527x over previous
#include <cuda_runtime.h>
#include <cuda_bf16.h>

#define TSTEPS  400
#define NEG_INF __int_as_float(0xff800000)
#define WSTART  224            // E window = steps [224, 384), 5 chunks of 32
#define HI0     26.0f          // safe upper bound on E_223 (true bound 24.9)

// Exact reference simulation for rare rows. Matches the JAX reference op-for-op.
__device__ __noinline__ float sm2_slow_row(const float* __restrict__ row) {
    float I = 1.0f, n = 0.0f, EF = 2.5f;
    for (int t = 0; t < TSTEPS; ++t) {
        float p = row[t];
        float q = p * 5.0f;
        bool correct = (q >= 3.0f);
        bool brk = (p == -1.0f);
        float In;
        if (n >= 2.0f)      In = I * EF;
        else if (n == 1.0f) In = 6.0f;
        else                In = 1.0f;
        if (!correct) In = 1.0f;
        if (!brk) I = In;
        I = fminf(fmaxf(I, 1.0f), 274.0f);
        float d = 5.0f - q;
        EF = EF + (0.1f - d * (0.08f + d * 0.02f));
        EF = fmaxf(EF, 1.3f);
        if (correct) n += 1.0f;
    }
    return I;
}

// delta(p) = 0.1 - d*(0.08 + 0.02 d),  d = 5 - 5p
__device__ __forceinline__ float delta_of(float pv) {
    float d  = fmaf(pv, -5.0f, 5.0f);
    float t2 = fmaf(d, 0.02f, 0.08f);
    return fmaf(-d, t2, 0.1f);
}

__global__ void __launch_bounds__(256)
sm2_kernel(const float* __restrict__ p, float* __restrict__ out, int B) {
    const unsigned FULL = 0xFFFFFFFFu;
    int gwarp = (blockIdx.x * blockDim.x + threadIdx.x) >> 5;
    int lane  = threadIdx.x & 31;
    int q     = lane & 7;                      // position within 8-lane row group

    int row0 = gwarp * 4 + (lane >> 3);
    int row  = (row0 < B) ? row0 : (B - 1);    // clamp: full warp active for shfl
    const float* rp = p + (size_t)row * TSTEPS;

    // ---- hoist ALL loads (10 LDG.128 in flight per lane) ----
    float4 c0 = *reinterpret_cast<const float4*>(rp + q * 4);                 // [0,32)
    float4 w0 = *reinterpret_cast<const float4*>(rp + WSTART +   0 + q * 4);
    float4 w1 = *reinterpret_cast<const float4*>(rp + WSTART +  32 + q * 4);
    float4 w2 = *reinterpret_cast<const float4*>(rp + WSTART +  64 + q * 4);
    float4 w3 = *reinterpret_cast<const float4*>(rp + WSTART +  96 + q * 4);
    float4 w4 = *reinterpret_cast<const float4*>(rp + WSTART + 128 + q * 4);
    float4 t0 = *reinterpret_cast<const float4*>(rp + 384);                   // broadcast
    float4 t1 = *reinterpret_cast<const float4*>(rp + 388);
    float4 t2 = *reinterpret_cast<const float4*>(rp + 392);
    float4 t3 = *reinterpret_cast<const float4*>(rp + 396);

    // ---- cnt2: corrects in steps [0,32) ----
    int cnt2;
    {
        float cv[4] = {c0.x, c0.y, c0.z, c0.w};
        int c = 0;
        #pragma unroll
        for (int k = 0; k < 4; ++k) c += (cv[k] * 5.0f >= 3.0f);
        c += __shfl_xor_sync(FULL, c, 1, 8);
        c += __shfl_xor_sync(FULL, c, 2, 8);
        c += __shfl_xor_sync(FULL, c, 4, 8);
        cnt2 = c;
    }

    // ---- window composition (S, M): E_383 = max(E_223 + S, M) ----
    float S = 0.0f, M = NEG_INF;
    float4 wbuf[5] = {w0, w1, w2, w3, w4};
    #pragma unroll
    for (int j = 0; j < 5; ++j) {
        float4 v = wbuf[j];
        float pv[4] = {v.x, v.y, v.z, v.w};
        float s = 0.0f, m = NEG_INF;
        #pragma unroll
        for (int k = 0; k < 4; ++k) {
            float dl = delta_of(pv[k]);
            m = fmaxf(m + dl, 1.3f);
            s += dl;
        }
        // Ordered tree reduce across the 8 lanes (leader q==0 gets full chunk).
        #pragma unroll
        for (int off = 1; off <= 4; off <<= 1) {
            float so = __shfl_down_sync(FULL, s, off, 8);
            float mo = __shfl_down_sync(FULL, m, off, 8);
            m = fmaxf(m + so, mo);
            s = s + so;
        }
        M = fmaxf(M + s, m);
        S = S + s;
    }
    float Sg = __shfl_sync(FULL, S, 0, 8);
    float Mg = __shfl_sync(FULL, M, 0, 8);

    // Collapse test: floor bound inside the window makes history irrelevant.
    bool exact = (Mg >= HI0 + Sg);
    float E = Mg;                    // E_383 when collapsed

    // ---- tail t = 384..399: sequential on all 8 lanes (broadcast regs) ----
    float Eh[16];
    unsigned mask = 0u;
    float4 tb[4] = {t0, t1, t2, t3};
    #pragma unroll
    for (int j = 0; j < 4; ++j) {
        float pv[4] = {tb[j].x, tb[j].y, tb[j].z, tb[j].w};
        #pragma unroll
        for (int k = 0; k < 4; ++k) {
            E = fmaxf(E + delta_of(pv[k]), 1.3f);
            Eh[j * 4 + k] = E;
            mask |= (pv[k] * 5.0f >= 3.0f) ? (1u << (j * 4 + k)) : 0u;
        }
    }

    // L = trailing-correct run length within last 16 steps (mask==0xFFFF -> 32).
    int L = __clz(((~mask) & 0xFFFFu) << 16);

    float I;
    if (L <= 15 && cnt2 >= 2 && exact) {
        float prod = 1.0f;
        #pragma unroll
        for (int j = 0; j < 15; ++j)
            if (j >= 15 - L) prod = fminf(prod * Eh[j], 274.0f);
        I = (L == 0) ? 1.0f : prod;
    } else {
        I = sm2_slow_row(rp);        // rare; group-uniform divergence
    }

    if (q == 0 && row0 < B)
        out[row] = fminf(2.0f * I, 274.0f);
}

extern "C" void kernel_launch(void* const* d_in, const int* in_sizes, int n_in,
                              void* d_out, int out_size) {
    const float* p = (const float*)d_in[0];
    float* out = (float*)d_out;
    int B = out_size;
    int rowsPerBlock = 32;               // 256 threads = 8 warps * 4 rows
    int blocks = (B + rowsPerBlock - 1) / rowsPerBlock;
    sm2_kernel<<<blocks, 256>>>(p, out, B);
}